// round 9
// baseline (speedup 1.0000x reference)
#include <cuda_runtime.h>
#include <cstdint>

// NormmaxBisect, alpha=1.5, d=2048: p = clamp(x - tau, 0)^2 / sum(...),
// tau solves sum(clamp(x - tau, 0)^3) = 1.
//
// TWO warps per row (half-row each), 4 rows per 256-thread block, rows coupled
// only through pair-scoped named barriers. Row halves live in smem (cp.async).
// Actives (x > rowmax-1) are compacted into fixed per-warp list segments;
// solver = 2 ballot-search rounds (33-way bracket split -> width 9e-4) +
// 3 Newton iterations run redundantly by every lane of both warps.
// Ultra-rare overflow rows take a pair-synchronized full-row bisection.

#define D 2048
#define HALF (D / 2)            // elements per warp
#define RPB 4                   // rows per block
#define THREADS (RPB * 64)
#define HSEG 128                // list segment per warp
#define NROUNDS 2
#define NN 3
#define NB_FB 22
#define DM0 0.9779029130879204f // 1 - (1/2048)^0.5

#define PAIR_BAR(id) asm volatile("bar.sync %0, 64;" :: "r"(id) : "memory")

static __device__ __forceinline__ float warp_sum(float v) {
    #pragma unroll
    for (int o = 16; o; o >>= 1) v += __shfl_xor_sync(0xffffffffu, v, o);
    return v;
}
static __device__ __forceinline__ float warp_max(float v) {
    #pragma unroll
    for (int o = 16; o; o >>= 1) v = fmaxf(v, __shfl_xor_sync(0xffffffffu, v, o));
    return v;
}

__global__ __launch_bounds__(THREADS, 5)
void normmax_pair_kernel(const float* __restrict__ X, float* __restrict__ O, int nrows) {
    __shared__ float4 srow[RPB][D / 4];          // 32 KB
    __shared__ float  slist[RPB][2 * HSEG];      //  4 KB
    __shared__ float  smax[RPB][2];
    __shared__ int    scnt[RPB][2];
    __shared__ float  sred[RPB][2][2];           // fallback partial sums

    const int wid  = threadIdx.x >> 5;           // 0..7
    const int lane = threadIdx.x & 31;
    const int rl   = wid >> 1;                   // row within block 0..3
    const int h    = wid & 1;                    // half index 0/1
    const int row  = blockIdx.x * RPB + rl;
    if (row >= nrows) return;
    const int bar = rl + 1;                      // named barrier id 1..4

    float4* r = srow[rl] + h * (HALF / 4);       // this warp's half (8 float4/lane)
    float*  lst = slist[rl];

    const float4* __restrict__ src =
        reinterpret_cast<const float4*>(X + (size_t)row * D + h * HALF);

    // ---- half-row -> smem via cp.async (MLP=8/lane, no register staging) ----
    #pragma unroll
    for (int j = 0; j < 8; ++j) {
        uint32_t sa = (uint32_t)__cvta_generic_to_shared(&r[j * 32 + lane]);
        asm volatile("cp.async.cg.shared.global [%0], [%1], 16;\n"
                     :: "r"(sa), "l"(src + j * 32 + lane));
    }
    asm volatile("cp.async.commit_group;\n");
    asm volatile("cp.async.wait_group 0;\n" ::: "memory");
    // each lane only reads back slots it wrote before the pair barrier

    // ---- warp max over own half ----
    float mx = -3.4e38f;
    #pragma unroll
    for (int j = 0; j < 8; ++j) {
        float4 t = r[j * 32 + lane];
        mx = fmaxf(mx, fmaxf(fmaxf(t.x, t.y), fmaxf(t.z, t.w)));
    }
    mx = warp_max(mx);
    if (lane == 0) smax[rl][h] = mx;
    PAIR_BAR(bar);
    const float thr = fmaxf(smax[rl][0], smax[rl][1]) - 1.0f;   // = tau_lo

    // ---- count actives in own half + warp prefix (deterministic order) ----
    int cnt = 0;
    #pragma unroll
    for (int j = 0; j < 8; ++j) {
        float4 t = r[j * 32 + lane];
        cnt += (t.x > thr) + (t.y > thr) + (t.z > thr) + (t.w > thr);
    }
    int pre = cnt;
    #pragma unroll
    for (int o = 1; o < 32; o <<= 1) {
        int t = __shfl_up_sync(0xffffffffu, pre, o);
        if (lane >= o) pre += t;
    }
    const int wtot = __shfl_sync(0xffffffffu, pre, 31);

    // ---- compact own actives into fixed segment [h*HSEG, ...) ----
    if (wtot <= HSEG) {
        int k = h * HSEG + (pre - cnt);
        #pragma unroll
        for (int j = 0; j < 8; ++j) {
            float4 t = r[j * 32 + lane];
            if (t.x > thr) lst[k++] = t.x;
            if (t.y > thr) lst[k++] = t.y;
            if (t.z > thr) lst[k++] = t.z;
            if (t.w > thr) lst[k++] = t.w;
        }
    }
    if (lane == 0) scnt[rl][h] = wtot;
    PAIR_BAR(bar);
    const int cnt0 = scnt[rl][0];
    const int cnt1 = scnt[rl][1];

    float tau, inv;
    if (cnt0 <= HSEG && cnt1 <= HSEG) {
        // ---- 2 ballot-search rounds over the list (both warps, redundant) ----
        float lo = thr;              // f(lo) >= 0 guaranteed
        float wd = DM0;
        #pragma unroll
        for (int rnd = 0; rnd < NROUNDS; ++rnd) {
            const float step = wd * (1.0f / 33.0f);
            const float tm = lo + step * (float)(lane + 1);
            float s3 = 0.0f;
            for (int i = 0; i < cnt0; ++i) {                  // LDS broadcast
                float c = fmaxf(lst[i] - tm, 0.0f);
                s3 = fmaf(c * c, c, s3);
            }
            for (int i = 0; i < cnt1; ++i) {
                float c = fmaxf(lst[HSEG + i] - tm, 0.0f);
                s3 = fmaf(c * c, c, s3);
            }
            const unsigned b = __ballot_sync(0xffffffffu, s3 >= 1.0f);
            const int m = 32 - __clz(b);        // satisfying lanes contiguous from 0
            lo += step * (float)m;              // f(lo) still >= 0
            wd = step;
        }

        // ---- 3 Newton steps, every lane redundant (warp-uniform tau) ----
        tau = lo;
        #pragma unroll
        for (int it = 0; it < NN; ++it) {
            float s2 = 0.0f, s3 = 0.0f;
            for (int i = 0; i < cnt0; ++i) {
                float c = fmaxf(lst[i] - tau, 0.0f);
                float c2 = c * c;
                s2 += c2;
                s3 = fmaf(c2, c, s3);
            }
            for (int i = 0; i < cnt1; ++i) {
                float c = fmaxf(lst[HSEG + i] - tau, 0.0f);
                float c2 = c * c;
                s2 += c2;
                s3 = fmaf(c2, c, s3);
            }
            tau += __fdividef(s3 - 1.0f, 3.0f * s2);   // convex, from f>=0 side
        }
        // ---- normalization sum at final tau ----
        float s2 = 0.0f;
        for (int i = 0; i < cnt0; ++i) {
            float c = fmaxf(lst[i] - tau, 0.0f);
            s2 = fmaf(c, c, s2);
        }
        for (int i = 0; i < cnt1; ++i) {
            float c = fmaxf(lst[HSEG + i] - tau, 0.0f);
            s2 = fmaf(c, c, s2);
        }
        inv = __fdividef(1.0f, s2);
    } else {
        // ---- ultra-rare fallback: pair-synchronized full-row bisection ----
        float tau_lo = thr, dm = DM0;
        for (int it = 0; it < NB_FB + NN; ++it) {
            const bool newton_phase = (it >= NB_FB);
            float tm;
            if (!newton_phase) {
                dm *= 0.5f;
                tm = tau_lo + dm;
            } else {
                tm = tau_lo;
            }
            float l2 = 0.0f, l3 = 0.0f;
            #pragma unroll
            for (int j = 0; j < 8; ++j) {
                float4 t = r[j * 32 + lane];
                float cx = fmaxf(t.x - tm, 0.0f), cy = fmaxf(t.y - tm, 0.0f);
                float cz = fmaxf(t.z - tm, 0.0f), cw = fmaxf(t.w - tm, 0.0f);
                float c2x = cx * cx, c2y = cy * cy, c2z = cz * cz, c2w = cw * cw;
                l2 += c2x + c2y + c2z + c2w;
                l3 = fmaf(c2x, cx, l3); l3 = fmaf(c2y, cy, l3);
                l3 = fmaf(c2z, cz, l3); l3 = fmaf(c2w, cw, l3);
            }
            l2 = warp_sum(l2);
            l3 = warp_sum(l3);
            if (lane == 0) { sred[rl][h][0] = l2; sred[rl][h][1] = l3; }
            PAIR_BAR(bar);
            const float s2 = sred[rl][0][0] + sred[rl][1][0];
            const float s3 = sred[rl][0][1] + sred[rl][1][1];
            PAIR_BAR(bar);
            if (!newton_phase) {
                if (s3 >= 1.0f) tau_lo = tm;
            } else {
                tau_lo += __fdividef(s3 - 1.0f, 3.0f * s2);
            }
        }
        tau = tau_lo;
        // normalization: s2 at final tau
        float l2 = 0.0f;
        #pragma unroll
        for (int j = 0; j < 8; ++j) {
            float4 t = r[j * 32 + lane];
            float cx = fmaxf(t.x - tau, 0.0f), cy = fmaxf(t.y - tau, 0.0f);
            float cz = fmaxf(t.z - tau, 0.0f), cw = fmaxf(t.w - tau, 0.0f);
            l2 = fmaf(cx, cx, l2); l2 = fmaf(cy, cy, l2);
            l2 = fmaf(cz, cz, l2); l2 = fmaf(cw, cw, l2);
        }
        l2 = warp_sum(l2);
        if (lane == 0) sred[rl][h][0] = l2;
        PAIR_BAR(bar);
        inv = __fdividef(1.0f, sred[rl][0][0] + sred[rl][1][0]);
    }

    // ---- output own half: p = clamp(x - tau)^2 * inv ----
    float4* __restrict__ dst =
        reinterpret_cast<float4*>(O + (size_t)row * D + h * HALF);
    #pragma unroll
    for (int j = 0; j < 8; ++j) {
        float4 t = r[j * 32 + lane];
        float cx = fmaxf(t.x - tau, 0.0f), cy = fmaxf(t.y - tau, 0.0f);
        float cz = fmaxf(t.z - tau, 0.0f), cw = fmaxf(t.w - tau, 0.0f);
        float4 p;
        p.x = cx * cx * inv;
        p.y = cy * cy * inv;
        p.z = cz * cz * inv;
        p.w = cw * cw * inv;
        dst[j * 32 + lane] = p;
    }
}

extern "C" void kernel_launch(void* const* d_in, const int* in_sizes, int n_in,
                              void* d_out, int out_size) {
    const float* X = (const float*)d_in[0];
    float* O = (float*)d_out;
    const int nrows = in_sizes[0] / D;                 // 65536
    const int grid = (nrows + RPB - 1) / RPB;
    normmax_pair_kernel<<<grid, THREADS>>>(X, O, nrows);
}

// round 10
// speedup vs baseline: 1.3769x; 1.3769x over previous
#include <cuda_runtime.h>
#include <cstdint>

// NormmaxBisect, alpha=1.5, d=2048: p = clamp(x - tau, 0)^2 / sum(...),
// tau solves sum(clamp(x - tau, 0)^3) = 1.
//
// Sparse-output kernel. One warp per row, NO smem row buffer:
//  - row is read once (registers, two halves of 8 float4/lane)
//  - candidates (x > threshold) are compacted with indices into a small
//    per-warp smem list straight from registers; half 0 uses thr1 = wm1-1
//    (superset; wm1 = warp max of half 0 <= rowmax), half 1 uses the exact
//    thr = rowmax-1. Inactive list entries clamp to 0 in all solver sums.
//  - solver: 2 ballot-search rounds (33-way split -> bracket 9e-4) + 3 Newton
//    iterations computed redundantly by every lane (no reductions).
//  - output: zero-fill via STG.128 (p = 0 for all inactive elements exactly,
//    matching the reference) + scatter of the few nonzero p values.
// Rare rows whose candidate list overflows take a gmem-cached full-row solve.

#define D 2048
#define WARPS 8
#define THREADS 256
#define LISTCAP 224
#define NROUNDS 2
#define NN 3
#define NB_FB 22
#define DM0 0.9779029130879204f   // 1 - (1/2048)^0.5

static __device__ __forceinline__ float warp_max(float v) {
    #pragma unroll
    for (int o = 16; o; o >>= 1) v = fmaxf(v, __shfl_xor_sync(0xffffffffu, v, o));
    return v;
}
static __device__ __forceinline__ float warp_sum(float v) {
    #pragma unroll
    for (int o = 16; o; o >>= 1) v += __shfl_xor_sync(0xffffffffu, v, o);
    return v;
}

// ---- fallback full-row sums straight from gmem (L1/L2-resident after pass 1) ----
static __device__ __forceinline__ float s3_g(const float4* __restrict__ src, int lane, float tau) {
    float s3 = 0.0f;
    #pragma unroll 4
    for (int j = 0; j < 16; ++j) {
        float4 t = src[j * 32 + lane];
        float cx = fmaxf(t.x - tau, 0.0f), cy = fmaxf(t.y - tau, 0.0f);
        float cz = fmaxf(t.z - tau, 0.0f), cw = fmaxf(t.w - tau, 0.0f);
        s3 = fmaf(cx * cx, cx, s3); s3 = fmaf(cy * cy, cy, s3);
        s3 = fmaf(cz * cz, cz, s3); s3 = fmaf(cw * cw, cw, s3);
    }
    return warp_sum(s3);
}
static __device__ __forceinline__ void s23_g(const float4* __restrict__ src, int lane, float tau,
                                             float& s2o, float& s3o) {
    float s2 = 0.0f, s3 = 0.0f;
    #pragma unroll 4
    for (int j = 0; j < 16; ++j) {
        float4 t = src[j * 32 + lane];
        float cx = fmaxf(t.x - tau, 0.0f), cy = fmaxf(t.y - tau, 0.0f);
        float cz = fmaxf(t.z - tau, 0.0f), cw = fmaxf(t.w - tau, 0.0f);
        float c2x = cx * cx, c2y = cy * cy, c2z = cz * cz, c2w = cw * cw;
        s2 += c2x + c2y + c2z + c2w;
        s3 = fmaf(c2x, cx, s3); s3 = fmaf(c2y, cy, s3);
        s3 = fmaf(c2z, cz, s3); s3 = fmaf(c2w, cw, s3);
    }
    s2o = warp_sum(s2);
    s3o = warp_sum(s3);
}

__global__ __launch_bounds__(THREADS, 5)
void normmax_sparse_kernel(const float* __restrict__ X, float* __restrict__ O, int nrows) {
    __shared__ float lv[WARPS][LISTCAP];
    __shared__ int   li[WARPS][LISTCAP];

    const int wid  = threadIdx.x >> 5;
    const int lane = threadIdx.x & 31;
    const int w    = blockIdx.x * WARPS + wid;
    if (w >= nrows) return;
    float* Lv = lv[wid];
    int*   Li = li[wid];

    const float4* __restrict__ src = reinterpret_cast<const float4*>(X + (size_t)w * D);
    float4* __restrict__ dst       = reinterpret_cast<float4*>(O + (size_t)w * D);

    float4 f[8];

    // ================= half 0: elements [0, 1024) =================
    #pragma unroll
    for (int j = 0; j < 8; ++j) f[j] = src[j * 32 + lane];
    float lm = -3.4e38f;
    #pragma unroll
    for (int j = 0; j < 8; ++j)
        lm = fmaxf(lm, fmaxf(fmaxf(f[j].x, f[j].y), fmaxf(f[j].z, f[j].w)));
    const float wm1  = warp_max(lm);
    const float thr1 = wm1 - 1.0f;     // wm1 <= rowmax -> superset threshold

    int cnt = 0;
    #pragma unroll
    for (int j = 0; j < 8; ++j)
        cnt += (f[j].x > thr1) + (f[j].y > thr1) + (f[j].z > thr1) + (f[j].w > thr1);
    int pre = cnt;
    #pragma unroll
    for (int o = 1; o < 32; o <<= 1) {
        int t = __shfl_up_sync(0xffffffffu, pre, o);
        if (lane >= o) pre += t;
    }
    int total = __shfl_sync(0xffffffffu, pre, 31);
    bool ovf = total > LISTCAP;
    if (!ovf) {
        int k = pre - cnt;
        #pragma unroll
        for (int j = 0; j < 8; ++j) {
            const int e = 4 * (j * 32 + lane);
            if (f[j].x > thr1) { Lv[k] = f[j].x; Li[k] = e;     ++k; }
            if (f[j].y > thr1) { Lv[k] = f[j].y; Li[k] = e + 1; ++k; }
            if (f[j].z > thr1) { Lv[k] = f[j].z; Li[k] = e + 2; ++k; }
            if (f[j].w > thr1) { Lv[k] = f[j].w; Li[k] = e + 3; ++k; }
        }
    }

    // ================= half 1: elements [1024, 2048) =================
    #pragma unroll
    for (int j = 0; j < 8; ++j) f[j] = src[(j + 8) * 32 + lane];
    float lm2 = -3.4e38f;
    #pragma unroll
    for (int j = 0; j < 8; ++j)
        lm2 = fmaxf(lm2, fmaxf(fmaxf(f[j].x, f[j].y), fmaxf(f[j].z, f[j].w)));
    const float wm2 = warp_max(lm2);
    const float mx  = fmaxf(wm1, wm2);
    const float thr = mx - 1.0f;       // exact active threshold (= tau_lo)

    int cnt2 = 0;
    #pragma unroll
    for (int j = 0; j < 8; ++j)
        cnt2 += (f[j].x > thr) + (f[j].y > thr) + (f[j].z > thr) + (f[j].w > thr);
    int pre2 = cnt2;
    #pragma unroll
    for (int o = 1; o < 32; o <<= 1) {
        int t = __shfl_up_sync(0xffffffffu, pre2, o);
        if (lane >= o) pre2 += t;
    }
    const int tot2 = __shfl_sync(0xffffffffu, pre2, 31);
    if (total + tot2 > LISTCAP) ovf = true;
    if (!ovf) {
        int k = total + (pre2 - cnt2);
        #pragma unroll
        for (int j = 0; j < 8; ++j) {
            const int e = 4 * ((j + 8) * 32 + lane);
            if (f[j].x > thr) { Lv[k] = f[j].x; Li[k] = e;     ++k; }
            if (f[j].y > thr) { Lv[k] = f[j].y; Li[k] = e + 1; ++k; }
            if (f[j].z > thr) { Lv[k] = f[j].z; Li[k] = e + 2; ++k; }
            if (f[j].w > thr) { Lv[k] = f[j].w; Li[k] = e + 3; ++k; }
        }
    }
    total += tot2;
    __syncwarp();   // publish list (and order zero-fill below vs scatter later)

    if (!ovf) {
        // ---- zero-fill output row (p = 0 exactly for all inactive elements) ----
        const float4 z = make_float4(0.0f, 0.0f, 0.0f, 0.0f);
        #pragma unroll
        for (int j = 0; j < 16; ++j) dst[j * 32 + lane] = z;

        // ---- 2 ballot-search rounds: 33-way bracket split per round ----
        float lo = thr;              // f(lo) >= 0 guaranteed (max element gives c=1)
        float wd = DM0;
        #pragma unroll
        for (int rnd = 0; rnd < NROUNDS; ++rnd) {
            const float step = wd * (1.0f / 33.0f);
            const float tm = lo + step * (float)(lane + 1);
            float s3 = 0.0f;
            for (int i = 0; i < total; ++i) {            // LDS broadcast reads
                float c = fmaxf(Lv[i] - tm, 0.0f);
                s3 = fmaf(c * c, c, s3);
            }
            const unsigned b = __ballot_sync(0xffffffffu, s3 >= 1.0f);
            const int m = 32 - __clz(b);   // satisfying lanes contiguous from 0
            lo += step * (float)m;         // f(lo) still >= 0
            wd = step;
        }

        // ---- 3 Newton steps, every lane redundant (warp-uniform tau) ----
        float tau = lo;
        #pragma unroll
        for (int it = 0; it < NN; ++it) {
            float s2 = 0.0f, s3 = 0.0f;
            for (int i = 0; i < total; ++i) {
                float c = fmaxf(Lv[i] - tau, 0.0f);
                float c2 = c * c;
                s2 += c2;
                s3 = fmaf(c2, c, s3);
            }
            tau += __fdividef(s3 - 1.0f, 3.0f * s2);   // convex, from f>=0 side
        }
        // ---- normalization ----
        float s2 = 0.0f;
        for (int i = 0; i < total; ++i) {
            float c = fmaxf(Lv[i] - tau, 0.0f);
            s2 = fmaf(c, c, s2);
        }
        const float inv = __fdividef(1.0f, s2);

        // ---- scatter nonzero p (order zero-fill before cross-lane scatter) ----
        __syncwarp();
        float* __restrict__ orow = O + (size_t)w * D;
        for (int i = lane; i < total; i += 32) {
            const float c = fmaxf(Lv[i] - tau, 0.0f);
            if (c > 0.0f) orow[Li[i]] = c * c * inv;
        }
    } else {
        // ---- rare fallback: full-row solve reading gmem (cached after pass 1) ----
        float tau_lo = thr, dm = DM0;
        for (int it = 0; it < NB_FB; ++it) {
            dm *= 0.5f;
            const float tm = tau_lo + dm;
            if (s3_g(src, lane, tm) >= 1.0f) tau_lo = tm;
        }
        float tau = tau_lo;
        for (int it = 0; it < NN; ++it) {
            float rs2, rs3;
            s23_g(src, lane, tau, rs2, rs3);
            tau += __fdividef(rs3 - 1.0f, 3.0f * rs2);
        }
        float s2, dummy;
        s23_g(src, lane, tau, s2, dummy);
        const float inv = __fdividef(1.0f, s2);

        // full-row output (same lane->address mapping, per-thread ordering safe)
        #pragma unroll 4
        for (int j = 0; j < 16; ++j) {
            float4 t = src[j * 32 + lane];
            float cx = fmaxf(t.x - tau, 0.0f), cy = fmaxf(t.y - tau, 0.0f);
            float cz = fmaxf(t.z - tau, 0.0f), cw = fmaxf(t.w - tau, 0.0f);
            float4 p;
            p.x = cx * cx * inv;
            p.y = cy * cy * inv;
            p.z = cz * cz * inv;
            p.w = cw * cw * inv;
            dst[j * 32 + lane] = p;
        }
    }
}

extern "C" void kernel_launch(void* const* d_in, const int* in_sizes, int n_in,
                              void* d_out, int out_size) {
    const float* X = (const float*)d_in[0];
    float* O = (float*)d_out;
    const int nrows = in_sizes[0] / D;                 // 65536
    const int grid = (nrows + WARPS - 1) / WARPS;
    normmax_sparse_kernel<<<grid, THREADS>>>(X, O, nrows);
}